// round 10
// baseline (speedup 1.0000x reference)
#include <cuda_runtime.h>
#include <cstdint>

#define DIMK   256
#define NOUT   512
#define MROWS  32768
#define NEMB   255
#define NEDGE  4194304

typedef unsigned int u32;

// device scratch
__device__ float4 g_xpad[MROWS];
__device__ u32    g_Wfrag[NOUT * DIMK];           // W  tf32, fragment order
__device__ u32    g_Afrag[(size_t)MROWS * DIMK];  // h  tf32, fragment order (32MB)

// smem: 4 stages x (A 8KB + B 8KB) = 64KB
#define STAGE_BYTES 16384
#define SM_SIZE     (4 * STAGE_BYTES)

__device__ __forceinline__ u32 f2tf32(float v) {
    u32 r; asm("cvt.rna.tf32.f32 %0, %1;" : "=r"(r) : "f"(v)); return r;
}
__device__ __forceinline__ u32 smem_u32(const void* p) {
    u32 a;
    asm("{ .reg .u64 t; cvta.to.shared.u64 t, %1; cvt.u32.u64 %0, t; }" : "=r"(a) : "l"(p));
    return a;
}
__device__ __forceinline__ void cp16(u32 dst, const void* src) {
    asm volatile("cp.async.cg.shared.global [%0], [%1], 16;" :: "r"(dst), "l"(src));
}
#define CP_COMMIT() asm volatile("cp.async.commit_group;" ::: "memory")
#define CP_WAIT2()  asm volatile("cp.async.wait_group 2;" ::: "memory")

__device__ __forceinline__ void mma_tf32(float* c, uint4 a, uint2 b) {
    asm volatile(
        "mma.sync.aligned.m16n8k8.row.col.f32.tf32.tf32.f32 "
        "{%0,%1,%2,%3}, {%4,%5,%6,%7}, {%8,%9}, {%0,%1,%2,%3};"
        : "+f"(c[0]), "+f"(c[1]), "+f"(c[2]), "+f"(c[3])
        : "r"(a.x), "r"(a.y), "r"(a.z), "r"(a.w), "r"(b.x), "r"(b.y));
}

// ---------------------------------------------------------------------------
// Prologue:
// blocks 0..1023    : g_Afrag (h, tf32, fragment order; per-32k-chunk blocks)
// blocks 1024..1151 : g_Wfrag
// blocks 1152..1279 : pad x -> float4
// ---------------------------------------------------------------------------
__global__ __launch_bounds__(256) void prologue_kernel(
    const float* __restrict__ x,
    const float* __restrict__ W,
    const float* __restrict__ charges,
    const int*   __restrict__ cats,
    const float* __restrict__ nmask,
    const float* __restrict__ emb)
{
    int bid = blockIdx.x, tid = threadIdx.x;
    if (bid < 1024) {
        #pragma unroll
        for (int i = 0; i < 8; i++) {
            int q     = bid * 2048 + i * 256 + tid;   // uint4 index
            int lane  = q & 31;
            int frag  = (q >> 5) & 31;
            int kc    = (q >> 10) & 7;
            int mb    = q >> 13;
            int tile_m = frag >> 2;
            int tile_k = frag & 3;
            int m0 = mb * 128 + tile_m * 16 + (lane >> 2);
            int k0 = kc * 32 + tile_k * 8 + (lane & 3);
            uint4 v;
            u32* vv = (u32*)&v;
            #pragma unroll
            for (int reg = 0; reg < 4; reg++) {
                int m = m0 + 8 * (reg & 1);
                int k = k0 + 4 * (reg >> 1);
                float msk = __ldg(&nmask[m]);
                float h = (k == 0) ? __ldg(&charges[m]) * msk
                                   : __ldg(&emb[__ldg(&cats[m]) * NEMB + k - 1]) * msk;
                vv[reg] = f2tf32(h);
            }
            ((uint4*)g_Afrag)[q] = v;
        }
    } else if (bid < 1152) {
        int b = bid - 1024;
        #pragma unroll
        for (int i = 0; i < 4; i++) {
            int fidx  = b * 1024 + i * 256 + tid;
            int reg   = fidx & 1;
            int lane  = (fidx >> 1) & 31;
            int tk    = (fidx >> 6) & 3;
            int tn    = (fidx >> 8) & 15;
            int kc    = (fidx >> 12) & 7;
            int nb    = fidx >> 15;
            int n = nb * 128 + tn * 8 + (lane >> 2);
            int k = kc * 32 + tk * 8 + (lane & 3) + 4 * reg;
            g_Wfrag[fidx] = f2tf32(W[k * NOUT + n]);
        }
    } else {
        int i = (bid - 1152) * 256 + tid;
        if (i < MROWS)
            g_xpad[i] = make_float4(x[3 * i], x[3 * i + 1], x[3 * i + 2], 0.f);
    }
}

// ---------------------------------------------------------------------------
// Fused kernel. GEMM blocks (bidx%3==0): 128x128 tile, 8 warps (4Mx2N),
// K split into 16 chunks of 16, 4-stage cp.async pipeline, one sync per chunk:
//   [wait_group 2 -> syncthreads -> issue load(c+3) (or EMPTY commit) -> MMA(c)]
// The unconditional commit keeps the "exactly 2 newer groups at the wait"
// invariant valid through the tail (this was the R9 race).
// ---------------------------------------------------------------------------
__global__ __launch_bounds__(256, 2) void fused_kernel(
    const float* __restrict__ bias,    // [512]
    const int*   __restrict__ edges,   // [2,E]
    float*       __restrict__ out_p,   // [32768,512]
    float*       __restrict__ radial,  // [E]
    float*       __restrict__ cd)      // [E,3]
{
    extern __shared__ char sm[];
    const int tid  = threadIdx.x;
    const int bidx = blockIdx.x;

    if (bidx % 3 == 0) {
        // =========================== GEMM ===========================
        const int g  = bidx / 3;
        const int bn = (g & 3) * 128;
        const int bm = (g >> 2) * 128;
        const int wid = tid >> 5;
        const int lid = tid & 31;
        const int warp_m = wid & 3;
        const int warp_n = wid >> 2;
        const u32 smb = smem_u32(sm);

        // base of this block's 32k-chunk arrays (uint4 units)
        const uint4* Asrc = (const uint4*)g_Afrag + (size_t)((bm >> 7) * 8) * 1024;
        const uint4* Bsrc = (const uint4*)g_Wfrag + (size_t)((bn >> 7) * 8) * 1024;

        // chunk c (0..15) -> stage s. c&1 selects tile_k half of the 32k chunk.
        auto loadAB = [&](int c, int s) {
            const int kc = c >> 1;
            const int h2 = (c & 1) * 2;
            const u32 base = smb + s * STAGE_BYTES;
            const uint4* a = Asrc + kc * 1024;
            const uint4* b = Bsrc + kc * 1024;
            #pragma unroll
            for (int i = 0; i < 2; i++) {
                // A: 512 uint4. fl = tile_m*2+tkl -> src frag = (fl>>1)*4+h2+(fl&1)
                int qa = tid + i * 256;
                int fl = qa >> 5;
                int sa = (((fl >> 1) * 4 + h2 + (fl & 1)) * 32) + (qa & 31);
                cp16(base + qa * 16, a + sa);
                // B: 512 uint4. seg = tn*2+tkl (16 uint4 per seg)
                int qb = tid + i * 256;
                int seg = qb >> 4;
                int sb = (((seg >> 1) * 4 + h2 + (seg & 1)) * 16) + (qb & 15);
                cp16(base + 8192 + qb * 16, b + sb);
            }
            CP_COMMIT();
        };

        float acc[2][8][4];
        #pragma unroll
        for (int t = 0; t < 2; t++)
            #pragma unroll
            for (int j = 0; j < 8; j++)
                #pragma unroll
                for (int q = 0; q < 4; q++) acc[t][j][q] = 0.f;

        loadAB(0, 0);
        loadAB(1, 1);
        loadAB(2, 2);

        #pragma unroll 1
        for (int c = 0; c < 16; c++) {
            const int s = c & 3;
            CP_WAIT2();
            __syncthreads();
            if (c + 3 < 16) loadAB(c + 3, (c + 3) & 3);
            else            CP_COMMIT();          // empty group: keeps wait invariant

            const u32* Asm = (const u32*)(sm + s * STAGE_BYTES);
            const u32* Bsm = (const u32*)(sm + s * STAGE_BYTES + 8192);
            #pragma unroll
            for (int tkl = 0; tkl < 2; tkl++) {
                uint4 afr[2];
                #pragma unroll
                for (int t = 0; t < 2; t++)
                    afr[t] = *(const uint4*)&Asm[(((warp_m * 2 + t) * 2 + tkl) * 32 + lid) * 4];
                uint2 bfr[8];
                #pragma unroll
                for (int j = 0; j < 8; j++)
                    bfr[j] = *(const uint2*)&Bsm[(((warp_n * 8 + j) * 2 + tkl) * 32 + lid) * 2];
                #pragma unroll
                for (int t = 0; t < 2; t++)
                    #pragma unroll
                    for (int j = 0; j < 8; j++)
                        mma_tf32(acc[t][j], afr[t], bfr[j]);
            }
        }

        // epilogue: bias + float2 stores
        #pragma unroll
        for (int t = 0; t < 2; t++) {
            int m0 = bm + warp_m * 32 + t * 16 + (lid >> 2);
            #pragma unroll
            for (int j = 0; j < 8; j++) {
                int col = bn + warp_n * 64 + j * 8 + (lid & 3) * 2;
                float2 bv = __ldg((const float2*)&bias[col]);
                float2 v0, v1;
                v0.x = acc[t][j][0] + bv.x; v0.y = acc[t][j][1] + bv.y;
                v1.x = acc[t][j][2] + bv.x; v1.y = acc[t][j][3] + bv.y;
                *(float2*)&out_p[(size_t)m0 * NOUT + col] = v0;
                *(float2*)&out_p[(size_t)(m0 + 8) * NOUT + col] = v1;
            }
        }
    } else {
        // =========================== edges ===========================
        const int eid  = bidx - (bidx + 2) / 3;   // 0..2047
        const int base = eid * 2048;
        float* stage = (float*)sm;                // 1536 floats

        #pragma unroll 1
        for (int r = 0; r < 4; r++) {
            int e0 = base + r * 512 + tid;
            int e1 = e0 + 256;
            int ra = __ldg(&edges[e0]);
            int rb = __ldg(&edges[e1]);
            int ca = __ldg(&edges[NEDGE + e0]);
            int cb = __ldg(&edges[NEDGE + e1]);
            float4 pa = __ldg(&g_xpad[ra]);
            float4 pb = __ldg(&g_xpad[rb]);
            float4 qa = __ldg(&g_xpad[ca]);
            float4 qb = __ldg(&g_xpad[cb]);

            float dax = pa.x - qa.x, day = pa.y - qa.y, daz = pa.z - qa.z;
            float dbx = pb.x - qb.x, dby = pb.y - qb.y, dbz = pb.z - qb.z;
            float rada = dax * dax + day * day + daz * daz;
            float radb = dbx * dbx + dby * dby + dbz * dbz;
            float inva = 1.0f / (sqrtf(rada + 1e-8f) + 1.0f);
            float invb = 1.0f / (sqrtf(radb + 1e-8f) + 1.0f);

            radial[e0] = rada;
            radial[e1] = radb;

            stage[tid * 3 + 0] = dax * inva;
            stage[tid * 3 + 1] = day * inva;
            stage[tid * 3 + 2] = daz * inva;
            stage[(tid + 256) * 3 + 0] = dbx * invb;
            stage[(tid + 256) * 3 + 1] = dby * invb;
            stage[(tid + 256) * 3 + 2] = dbz * invb;
            __syncthreads();

            float4* dst = (float4*)(cd + (size_t)(base + r * 512) * 3);
            const float4* s4 = (const float4*)stage;
            dst[tid] = s4[tid];
            if (tid < 128) dst[256 + tid] = s4[256 + tid];
            __syncthreads();
        }
    }
}

// ---------------------------------------------------------------------------
// inputs: 0 x, 1 categories, 2 charges, 3 edges, 4 node_mask, 5 edge_mask,
//         6 emb_table, 7 W, 8 b_lin
// output: parameters [32768*512] | radial [E] | coord_diff [E*3]
// ---------------------------------------------------------------------------
extern "C" void kernel_launch(void* const* d_in, const int* in_sizes, int n_in,
                              void* d_out, int out_size)
{
    const float* x       = (const float*)d_in[0];
    const int*   cats    = (const int*)  d_in[1];
    const float* charges = (const float*)d_in[2];
    const int*   edges   = (const int*)  d_in[3];
    const float* nmask   = (const float*)d_in[4];
    const float* emb     = (const float*)d_in[6];
    const float* W       = (const float*)d_in[7];
    const float* bias    = (const float*)d_in[8];

    float* out        = (float*)d_out;
    float* out_params = out;
    float* out_radial = out + (size_t)MROWS * NOUT;
    float* out_cd     = out_radial + NEDGE;

    cudaFuncSetAttribute(fused_kernel, cudaFuncAttributeMaxDynamicSharedMemorySize, SM_SIZE);

    prologue_kernel<<<1280, 256>>>(x, W, charges, cats, nmask, emb);
    fused_kernel<<<3072, 256, SM_SIZE>>>(bias, edges, out_params, out_radial, out_cd);
}

// round 11
// speedup vs baseline: 1.2338x; 1.2338x over previous
#include <cuda_runtime.h>
#include <cuda_fp16.h>
#include <cstdint>

#define DIMK   256
#define NOUT   512
#define MROWS  32768
#define NEMB   255
#define NEDGE  4194304

typedef unsigned int u32;

// device scratch
__device__ float4 g_xpad[MROWS];
__device__ u32    g_Wfrag[NOUT * DIMK / 2];            // W  fp16, frag order (256KB)
__device__ u32    g_Afrag[(size_t)MROWS * DIMK / 2];   // h  fp16, frag order (16MB)

// smem: 4 stages x (A 8KB + B 8KB) = 64KB
#define STAGE_BYTES 16384
#define SM_SIZE     (4 * STAGE_BYTES)

__device__ __forceinline__ u32 pack_h2(float lo, float hi) {
    __half2 h = __floats2half2_rn(lo, hi);   // lo -> .x (low 16), hi -> .y
    return *(u32*)&h;
}
__device__ __forceinline__ u32 smem_u32(const void* p) {
    u32 a;
    asm("{ .reg .u64 t; cvta.to.shared.u64 t, %1; cvt.u32.u64 %0, t; }" : "=r"(a) : "l"(p));
    return a;
}
__device__ __forceinline__ void cp16(u32 dst, const void* src) {
    asm volatile("cp.async.cg.shared.global [%0], [%1], 16;" :: "r"(dst), "l"(src));
}
#define CP_COMMIT() asm volatile("cp.async.commit_group;" ::: "memory")
#define CP_WAIT2()  asm volatile("cp.async.wait_group 2;" ::: "memory")

// fp16 m16n8k16, fp32 accumulate
__device__ __forceinline__ void mma_f16(float* c, uint4 a, uint2 b) {
    asm volatile(
        "mma.sync.aligned.m16n8k16.row.col.f32.f16.f16.f32 "
        "{%0,%1,%2,%3}, {%4,%5,%6,%7}, {%8,%9}, {%0,%1,%2,%3};"
        : "+f"(c[0]), "+f"(c[1]), "+f"(c[2]), "+f"(c[3])
        : "r"(a.x), "r"(a.y), "r"(a.z), "r"(a.w), "r"(b.x), "r"(b.y));
}

// ---------------------------------------------------------------------------
// Fragment layouts (m16n8k16):
// A chunk (mb,kc): 128 m x 32 k fp16 = 512 uint4.
//   uint4 idx in chunk = tile_m*64 + ks*32 + lane   (tile_m<8, ks<2)
//   m = mb*128 + tile_m*16 + lane/4 ;  k0 = kc*32 + ks*16 + (lane&3)*2
//   regs: a0=(m,k0|k0+1) a1=(m+8,k0|k0+1) a2=(m,k0+8|+9) a3=(m+8,k0+8|+9)
// B chunk (nb,kc): 128 n x 32 k fp16 = 1024 uint2.
//   uint2 idx in chunk = tile_n*64 + ks*32 + lane   (tile_n<16, ks<2)
//   n = nb*128 + tile_n*8 + lane/4 ;  k0 = kc*32 + ks*16 + (lane&3)*2
//   regs: b0=(k0,n|k0+1,n)  b1=(k0+8,n|k0+9,n)
// ---------------------------------------------------------------------------

__global__ __launch_bounds__(256) void prologue_kernel(
    const float* __restrict__ x,
    const float* __restrict__ W,
    const float* __restrict__ charges,
    const int*   __restrict__ cats,
    const float* __restrict__ nmask,
    const float* __restrict__ emb)
{
    int bid = blockIdx.x, tid = threadIdx.x;
    if (bid < 1024) {
        // g_Afrag: 1M uint4 total, 4 per thread
        #pragma unroll
        for (int i = 0; i < 4; i++) {
            int q      = bid * 1024 + i * 256 + tid;   // uint4 index
            int lane   = q & 31;
            int ks     = (q >> 5) & 1;
            int tile_m = (q >> 6) & 7;
            int kc     = (q >> 9) & 7;
            int mb     = q >> 12;
            int m  = mb * 128 + tile_m * 16 + (lane >> 2);
            int k0 = kc * 32 + ks * 16 + (lane & 3) * 2;

            float msk0 = __ldg(&nmask[m]);
            float msk1 = __ldg(&nmask[m + 8]);
            int   cat0 = __ldg(&cats[m]);
            int   cat1 = __ldg(&cats[m + 8]);
            auto hval = [&](int mm, float msk, int cat, int k) -> float {
                return (k == 0) ? __ldg(&charges[mm]) * msk
                                : __ldg(&emb[cat * NEMB + k - 1]) * msk;
            };
            uint4 v;
            v.x = pack_h2(hval(m,     msk0, cat0, k0),     hval(m,     msk0, cat0, k0 + 1));
            v.y = pack_h2(hval(m + 8, msk1, cat1, k0),     hval(m + 8, msk1, cat1, k0 + 1));
            v.z = pack_h2(hval(m,     msk0, cat0, k0 + 8), hval(m,     msk0, cat0, k0 + 9));
            v.w = pack_h2(hval(m + 8, msk1, cat1, k0 + 8), hval(m + 8, msk1, cat1, k0 + 9));
            ((uint4*)g_Afrag)[q] = v;
        }
    } else if (bid < 1152) {
        // g_Wfrag: 64K uint2 total, 2 per (block,thread) over 128 blocks
        int b = bid - 1024;
        #pragma unroll
        for (int i = 0; i < 2; i++) {
            int p      = b * 512 + i * 256 + tid;      // uint2 index
            int lane   = p & 31;
            int ks     = (p >> 5) & 1;
            int tile_n = (p >> 6) & 15;
            int kc     = (p >> 10) & 7;
            int nb     = p >> 13;
            int n  = nb * 128 + tile_n * 8 + (lane >> 2);
            int k0 = kc * 32 + ks * 16 + (lane & 3) * 2;
            uint2 v;
            v.x = pack_h2(W[k0 * NOUT + n],       W[(k0 + 1) * NOUT + n]);
            v.y = pack_h2(W[(k0 + 8) * NOUT + n], W[(k0 + 9) * NOUT + n]);
            ((uint2*)g_Wfrag)[p] = v;
        }
    } else {
        int i = (bid - 1152) * 256 + tid;
        if (i < MROWS)
            g_xpad[i] = make_float4(x[3 * i], x[3 * i + 1], x[3 * i + 2], 0.f);
    }
}

// ---------------------------------------------------------------------------
// Fused kernel. GEMM blocks (bidx%3==0): 128x128 tile, 8 warps (4Mx2N),
// K = 8 chunks of 32, 4-stage cp.async pipeline, one sync per chunk:
//   [wait_group 2 -> sync -> load(c+3) or EMPTY commit -> MMA(c)]
// ---------------------------------------------------------------------------
__global__ __launch_bounds__(256, 2) void fused_kernel(
    const float* __restrict__ bias,    // [512]
    const int*   __restrict__ edges,   // [2,E]
    float*       __restrict__ out_p,   // [32768,512]
    float*       __restrict__ radial,  // [E]
    float*       __restrict__ cd)      // [E,3]
{
    extern __shared__ char sm[];
    const int tid  = threadIdx.x;
    const int bidx = blockIdx.x;

    if (bidx % 3 == 0) {
        // =========================== GEMM ===========================
        const int g  = bidx / 3;
        const int bn = (g & 3) * 128;
        const int bm = (g >> 2) * 128;
        const int wid = tid >> 5;
        const int lid = tid & 31;
        const int warp_m = wid & 3;
        const int warp_n = wid >> 2;
        const u32 smb = smem_u32(sm);

        const uint4* Asrc = (const uint4*)g_Afrag + (size_t)((bm >> 7) * 8) * 512;
        const uint4* Bsrc = (const uint4*)g_Wfrag + (size_t)((bn >> 7) * 8) * 512;

        // chunk c (0..7) -> stage s: A 512 uint4 + B 512 uint4, flat copies
        auto loadAB = [&](int c, int s) {
            const u32 base = smb + s * STAGE_BYTES;
            const uint4* a = Asrc + c * 512;
            const uint4* b = Bsrc + c * 512;
            #pragma unroll
            for (int i = 0; i < 2; i++) {
                int e = tid + i * 256;
                cp16(base + e * 16, a + e);
                cp16(base + 8192 + e * 16, b + e);
            }
            CP_COMMIT();
        };

        float acc[2][8][4];
        #pragma unroll
        for (int t = 0; t < 2; t++)
            #pragma unroll
            for (int j = 0; j < 8; j++)
                #pragma unroll
                for (int q = 0; q < 4; q++) acc[t][j][q] = 0.f;

        loadAB(0, 0);
        loadAB(1, 1);
        loadAB(2, 2);

        #pragma unroll 1
        for (int c = 0; c < 8; c++) {
            const int s = c & 3;
            CP_WAIT2();
            __syncthreads();
            if (c + 3 < 8) loadAB(c + 3, (c + 3) & 3);
            else           CP_COMMIT();          // empty group: keeps wait invariant

            const uint4* Asm = (const uint4*)(sm + s * STAGE_BYTES);
            const uint2* Bsm = (const uint2*)(sm + s * STAGE_BYTES + 8192);
            #pragma unroll
            for (int ks = 0; ks < 2; ks++) {
                uint4 afr[2];
                #pragma unroll
                for (int t = 0; t < 2; t++)
                    afr[t] = Asm[(warp_m * 2 + t) * 64 + ks * 32 + lid];
                uint2 bfr[8];
                #pragma unroll
                for (int j = 0; j < 8; j++)
                    bfr[j] = Bsm[(warp_n * 8 + j) * 64 + ks * 32 + lid];
                #pragma unroll
                for (int t = 0; t < 2; t++)
                    #pragma unroll
                    for (int j = 0; j < 8; j++)
                        mma_f16(acc[t][j], afr[t], bfr[j]);
            }
        }

        // epilogue: bias + float2 stores (acc layout same as tf32 path)
        #pragma unroll
        for (int t = 0; t < 2; t++) {
            int m0 = bm + warp_m * 32 + t * 16 + (lid >> 2);
            #pragma unroll
            for (int j = 0; j < 8; j++) {
                int col = bn + warp_n * 64 + j * 8 + (lid & 3) * 2;
                float2 bv = __ldg((const float2*)&bias[col]);
                float2 v0, v1;
                v0.x = acc[t][j][0] + bv.x; v0.y = acc[t][j][1] + bv.y;
                v1.x = acc[t][j][2] + bv.x; v1.y = acc[t][j][3] + bv.y;
                *(float2*)&out_p[(size_t)m0 * NOUT + col] = v0;
                *(float2*)&out_p[(size_t)(m0 + 8) * NOUT + col] = v1;
            }
        }
    } else {
        // =========================== edges ===========================
        const int eid  = bidx - (bidx + 2) / 3;   // 0..2047
        const int base = eid * 2048;
        float* stage = (float*)sm;                // 1536 floats

        #pragma unroll 1
        for (int r = 0; r < 4; r++) {
            int e0 = base + r * 512 + tid;
            int e1 = e0 + 256;
            int ra = __ldg(&edges[e0]);
            int rb = __ldg(&edges[e1]);
            int ca = __ldg(&edges[NEDGE + e0]);
            int cb = __ldg(&edges[NEDGE + e1]);
            float4 pa = __ldg(&g_xpad[ra]);
            float4 pb = __ldg(&g_xpad[rb]);
            float4 qa = __ldg(&g_xpad[ca]);
            float4 qb = __ldg(&g_xpad[cb]);

            float dax = pa.x - qa.x, day = pa.y - qa.y, daz = pa.z - qa.z;
            float dbx = pb.x - qb.x, dby = pb.y - qb.y, dbz = pb.z - qb.z;
            float rada = dax * dax + day * day + daz * daz;
            float radb = dbx * dbx + dby * dby + dbz * dbz;
            float inva = 1.0f / (sqrtf(rada + 1e-8f) + 1.0f);
            float invb = 1.0f / (sqrtf(radb + 1e-8f) + 1.0f);

            radial[e0] = rada;
            radial[e1] = radb;

            stage[tid * 3 + 0] = dax * inva;
            stage[tid * 3 + 1] = day * inva;
            stage[tid * 3 + 2] = daz * inva;
            stage[(tid + 256) * 3 + 0] = dbx * invb;
            stage[(tid + 256) * 3 + 1] = dby * invb;
            stage[(tid + 256) * 3 + 2] = dbz * invb;
            __syncthreads();

            float4* dst = (float4*)(cd + (size_t)(base + r * 512) * 3);
            const float4* s4 = (const float4*)stage;
            dst[tid] = s4[tid];
            if (tid < 128) dst[256 + tid] = s4[256 + tid];
            __syncthreads();
        }
    }
}

// ---------------------------------------------------------------------------
// inputs: 0 x, 1 categories, 2 charges, 3 edges, 4 node_mask, 5 edge_mask,
//         6 emb_table, 7 W, 8 b_lin
// output: parameters [32768*512] | radial [E] | coord_diff [E*3]
// ---------------------------------------------------------------------------
extern "C" void kernel_launch(void* const* d_in, const int* in_sizes, int n_in,
                              void* d_out, int out_size)
{
    const float* x       = (const float*)d_in[0];
    const int*   cats    = (const int*)  d_in[1];
    const float* charges = (const float*)d_in[2];
    const int*   edges   = (const int*)  d_in[3];
    const float* nmask   = (const float*)d_in[4];
    const float* emb     = (const float*)d_in[6];
    const float* W       = (const float*)d_in[7];
    const float* bias    = (const float*)d_in[8];

    float* out        = (float*)d_out;
    float* out_params = out;
    float* out_radial = out + (size_t)MROWS * NOUT;
    float* out_cd     = out_radial + NEDGE;

    cudaFuncSetAttribute(fused_kernel, cudaFuncAttributeMaxDynamicSharedMemorySize, SM_SIZE);

    prologue_kernel<<<1280, 256>>>(x, W, charges, cats, nmask, emb);
    fused_kernel<<<3072, 256, SM_SIZE>>>(bias, edges, out_params, out_radial, out_cd);
}

// round 12
// speedup vs baseline: 1.3207x; 1.0705x over previous
#include <cuda_runtime.h>
#include <cuda_fp16.h>
#include <cstdint>

#define DIMK   256
#define NOUT   512
#define MROWS  32768
#define NEMB   255
#define NEDGE  4194304

typedef unsigned int u32;

// device scratch
__device__ float4 g_xpad[MROWS];
__device__ u32    g_Wfrag[NOUT * DIMK / 2];            // W  fp16, frag order (256KB)
__device__ u32    g_Afrag[(size_t)MROWS * DIMK / 2];   // h  fp16, frag order (16MB)

// smem: 4 stages x (A 8KB + B 4KB) = 48KB
#define STAGE_BYTES 12288
#define SM_SIZE     (4 * STAGE_BYTES)

__device__ __forceinline__ u32 pack_h2(float lo, float hi) {
    __half2 h = __floats2half2_rn(lo, hi);
    return *(u32*)&h;
}
__device__ __forceinline__ u32 smem_u32(const void* p) {
    u32 a;
    asm("{ .reg .u64 t; cvta.to.shared.u64 t, %1; cvt.u32.u64 %0, t; }" : "=r"(a) : "l"(p));
    return a;
}
__device__ __forceinline__ void cp16(u32 dst, const void* src) {
    asm volatile("cp.async.cg.shared.global [%0], [%1], 16;" :: "r"(dst), "l"(src));
}
#define CP_COMMIT() asm volatile("cp.async.commit_group;" ::: "memory")
#define CP_WAIT2()  asm volatile("cp.async.wait_group 2;" ::: "memory")

__device__ __forceinline__ void mma_f16(float* c, uint4 a, uint2 b) {
    asm volatile(
        "mma.sync.aligned.m16n8k16.row.col.f32.f16.f16.f32 "
        "{%0,%1,%2,%3}, {%4,%5,%6,%7}, {%8,%9}, {%0,%1,%2,%3};"
        : "+f"(c[0]), "+f"(c[1]), "+f"(c[2]), "+f"(c[3])
        : "r"(a.x), "r"(a.y), "r"(a.z), "r"(a.w), "r"(b.x), "r"(b.y));
}

// ---------------------------------------------------------------------------
// Fragment layouts (m16n8k16)  — unchanged from R11:
// A chunk (mb,kc): 128m x 32k fp16 = 512 uint4; idx = tile_m*64 + ks*32 + lane
// B chunk (nb,kc): 128n x 32k fp16 = 1024 uint2; idx = tile_n*64 + ks*32 + lane
// ---------------------------------------------------------------------------

__global__ __launch_bounds__(256) void prologue_kernel(
    const float* __restrict__ x,
    const float* __restrict__ W,
    const float* __restrict__ charges,
    const int*   __restrict__ cats,
    const float* __restrict__ nmask,
    const float* __restrict__ emb)
{
    int bid = blockIdx.x, tid = threadIdx.x;
    if (bid < 1024) {
        #pragma unroll
        for (int i = 0; i < 4; i++) {
            int q      = bid * 1024 + i * 256 + tid;   // uint4 index
            int lane   = q & 31;
            int ks     = (q >> 5) & 1;
            int tile_m = (q >> 6) & 7;
            int kc     = (q >> 9) & 7;
            int mb     = q >> 12;
            int m  = mb * 128 + tile_m * 16 + (lane >> 2);
            int k0 = kc * 32 + ks * 16 + (lane & 3) * 2;

            float msk0 = __ldg(&nmask[m]);
            float msk1 = __ldg(&nmask[m + 8]);
            int   cat0 = __ldg(&cats[m]);
            int   cat1 = __ldg(&cats[m + 8]);
            auto hval = [&](int mm, float msk, int cat, int k) -> float {
                return (k == 0) ? __ldg(&charges[mm]) * msk
                                : __ldg(&emb[cat * NEMB + k - 1]) * msk;
            };
            uint4 v;
            v.x = pack_h2(hval(m,     msk0, cat0, k0),     hval(m,     msk0, cat0, k0 + 1));
            v.y = pack_h2(hval(m + 8, msk1, cat1, k0),     hval(m + 8, msk1, cat1, k0 + 1));
            v.z = pack_h2(hval(m,     msk0, cat0, k0 + 8), hval(m,     msk0, cat0, k0 + 9));
            v.w = pack_h2(hval(m + 8, msk1, cat1, k0 + 8), hval(m + 8, msk1, cat1, k0 + 9));
            ((uint4*)g_Afrag)[q] = v;
        }
    } else if (bid < 1152) {
        int b = bid - 1024;
        #pragma unroll
        for (int i = 0; i < 2; i++) {
            int p      = b * 512 + i * 256 + tid;      // uint2 index
            int lane   = p & 31;
            int ks     = (p >> 5) & 1;
            int tile_n = (p >> 6) & 15;
            int kc     = (p >> 10) & 7;
            int nb     = p >> 13;
            int n  = nb * 128 + tile_n * 8 + (lane >> 2);
            int k0 = kc * 32 + ks * 16 + (lane & 3) * 2;
            uint2 v;
            v.x = pack_h2(W[k0 * NOUT + n],       W[(k0 + 1) * NOUT + n]);
            v.y = pack_h2(W[(k0 + 8) * NOUT + n], W[(k0 + 9) * NOUT + n]);
            ((uint2*)g_Wfrag)[p] = v;
        }
    } else {
        int i = (bid - 1152) * 256 + tid;
        if (i < MROWS)
            g_xpad[i] = make_float4(x[3 * i], x[3 * i + 1], x[3 * i + 2], 0.f);
    }
}

// ---------------------------------------------------------------------------
// Fused kernel, grid 4096: even bidx -> GEMM (2048 tiles of 128x64),
// odd bidx -> edges (2048 blocks x 2048 edges, sync-free).
// GEMM: 8 warps (4M x 2N), warp tile 32x32, K = 8 chunks of 32,
// 4-stage cp.async pipeline, one sync per chunk, tail empty-commits.
// ---------------------------------------------------------------------------
__global__ __launch_bounds__(256, 3) void fused_kernel(
    const float* __restrict__ bias,    // [512]
    const int*   __restrict__ edges,   // [2,E]
    float*       __restrict__ out_p,   // [32768,512]
    float*       __restrict__ radial,  // [E]
    float*       __restrict__ cd)      // [E,3]
{
    extern __shared__ char sm[];
    const int tid  = threadIdx.x;
    const int bidx = blockIdx.x;

    if ((bidx & 1) == 0) {
        // =========================== GEMM ===========================
        const int g  = bidx >> 1;            // 0..2047
        const int bn = (g & 7) * 64;
        const int bm = (g >> 3) * 128;
        const int wid = tid >> 5;
        const int lid = tid & 31;
        const int warp_m = wid & 3;          // 0..3
        const int warp_n = wid >> 2;         // 0..1
        const u32 smb = smem_u32(sm);

        const uint4* Asrc = (const uint4*)g_Afrag + (size_t)((bm >> 7) * 8) * 512;
        // B: nb = bn>>7 selects 128-wide group; half = (bn>>6)&1 selects 8 tile_n
        const uint4* Bsrc = (const uint4*)g_Wfrag
                          + (size_t)((bn >> 7) * 8) * 512 + ((bn >> 6) & 1) * 256;

        // chunk c (0..7) -> stage s: A 512 uint4 + B 256 uint4 (contiguous)
        auto loadAB = [&](int c, int s) {
            const u32 base = smb + s * STAGE_BYTES;
            const uint4* a = Asrc + c * 512;
            const uint4* b = Bsrc + c * 512;
            cp16(base + tid * 16,             a + tid);
            cp16(base + (tid + 256) * 16,     a + tid + 256);
            cp16(base + 8192 + tid * 16,      b + tid);
            CP_COMMIT();
        };

        float acc[2][4][4];
        #pragma unroll
        for (int t = 0; t < 2; t++)
            #pragma unroll
            for (int j = 0; j < 4; j++)
                #pragma unroll
                for (int q = 0; q < 4; q++) acc[t][j][q] = 0.f;

        loadAB(0, 0);
        loadAB(1, 1);
        loadAB(2, 2);

        #pragma unroll 1
        for (int c = 0; c < 8; c++) {
            const int s = c & 3;
            CP_WAIT2();
            __syncthreads();
            if (c + 3 < 8) loadAB(c + 3, (c + 3) & 3);
            else           CP_COMMIT();          // empty group: keeps wait invariant

            const uint4* Asm = (const uint4*)(sm + s * STAGE_BYTES);
            const uint2* Bsm = (const uint2*)(sm + s * STAGE_BYTES + 8192);
            #pragma unroll
            for (int ks = 0; ks < 2; ks++) {
                uint4 afr[2];
                #pragma unroll
                for (int t = 0; t < 2; t++)
                    afr[t] = Asm[(warp_m * 2 + t) * 64 + ks * 32 + lid];
                uint2 bfr[4];
                #pragma unroll
                for (int j = 0; j < 4; j++)
                    bfr[j] = Bsm[(warp_n * 4 + j) * 64 + ks * 32 + lid];
                #pragma unroll
                for (int t = 0; t < 2; t++)
                    #pragma unroll
                    for (int j = 0; j < 4; j++)
                        mma_f16(acc[t][j], afr[t], bfr[j]);
            }
        }

        // epilogue: bias + float2 stores
        #pragma unroll
        for (int t = 0; t < 2; t++) {
            int m0 = bm + warp_m * 32 + t * 16 + (lid >> 2);
            #pragma unroll
            for (int j = 0; j < 4; j++) {
                int col = bn + warp_n * 32 + j * 8 + (lid & 3) * 2;
                float2 bv = __ldg((const float2*)&bias[col]);
                float2 v0, v1;
                v0.x = acc[t][j][0] + bv.x; v0.y = acc[t][j][1] + bv.y;
                v1.x = acc[t][j][2] + bv.x; v1.y = acc[t][j][3] + bv.y;
                *(float2*)&out_p[(size_t)m0 * NOUT + col] = v0;
                *(float2*)&out_p[(size_t)(m0 + 8) * NOUT + col] = v1;
            }
        }
    } else {
        // ================= edges: sync-free, 4 consecutive per thread =========
        const int eid  = bidx >> 1;               // 0..2047
        const int b4   = eid * 512 + tid;         // first int4 index of this thread
        const int4* rowp = (const int4*)edges;
        const int4* colp = (const int4*)(edges + NEDGE);

        #pragma unroll 1
        for (int it = 0; it < 2; it++) {
            int q4 = b4 + it * 256;               // int4 / float4 index (4 edges)
            int4 r = __ldg(&rowp[q4]);
            int4 c = __ldg(&colp[q4]);
            float4 p0 = __ldg(&g_xpad[r.x]);
            float4 p1 = __ldg(&g_xpad[r.y]);
            float4 p2 = __ldg(&g_xpad[r.z]);
            float4 p3 = __ldg(&g_xpad[r.w]);
            float4 q0 = __ldg(&g_xpad[c.x]);
            float4 q1 = __ldg(&g_xpad[c.y]);
            float4 q2 = __ldg(&g_xpad[c.z]);
            float4 q3 = __ldg(&g_xpad[c.w]);

            float d0x = p0.x - q0.x, d0y = p0.y - q0.y, d0z = p0.z - q0.z;
            float d1x = p1.x - q1.x, d1y = p1.y - q1.y, d1z = p1.z - q1.z;
            float d2x = p2.x - q2.x, d2y = p2.y - q2.y, d2z = p2.z - q2.z;
            float d3x = p3.x - q3.x, d3y = p3.y - q3.y, d3z = p3.z - q3.z;

            float4 rad;
            rad.x = d0x*d0x + d0y*d0y + d0z*d0z;
            rad.y = d1x*d1x + d1y*d1y + d1z*d1z;
            rad.z = d2x*d2x + d2y*d2y + d2z*d2z;
            rad.w = d3x*d3x + d3y*d3y + d3z*d3z;

            float i0 = 1.0f / (sqrtf(rad.x + 1e-8f) + 1.0f);
            float i1 = 1.0f / (sqrtf(rad.y + 1e-8f) + 1.0f);
            float i2 = 1.0f / (sqrtf(rad.z + 1e-8f) + 1.0f);
            float i3 = 1.0f / (sqrtf(rad.w + 1e-8f) + 1.0f);

            ((float4*)radial)[q4] = rad;

            float4* dst = (float4*)cd + (size_t)q4 * 3;
            dst[0] = make_float4(d0x * i0, d0y * i0, d0z * i0, d1x * i1);
            dst[1] = make_float4(d1y * i1, d1z * i1, d2x * i2, d2y * i2);
            dst[2] = make_float4(d2z * i2, d3x * i3, d3y * i3, d3z * i3);
        }
    }
}

// ---------------------------------------------------------------------------
// inputs: 0 x, 1 categories, 2 charges, 3 edges, 4 node_mask, 5 edge_mask,
//         6 emb_table, 7 W, 8 b_lin
// output: parameters [32768*512] | radial [E] | coord_diff [E*3]
// ---------------------------------------------------------------------------
extern "C" void kernel_launch(void* const* d_in, const int* in_sizes, int n_in,
                              void* d_out, int out_size)
{
    const float* x       = (const float*)d_in[0];
    const int*   cats    = (const int*)  d_in[1];
    const float* charges = (const float*)d_in[2];
    const int*   edges   = (const int*)  d_in[3];
    const float* nmask   = (const float*)d_in[4];
    const float* emb     = (const float*)d_in[6];
    const float* W       = (const float*)d_in[7];
    const float* bias    = (const float*)d_in[8];

    float* out        = (float*)d_out;
    float* out_params = out;
    float* out_radial = out + (size_t)MROWS * NOUT;
    float* out_cd     = out_radial + NEDGE;

    cudaFuncSetAttribute(fused_kernel, cudaFuncAttributeMaxDynamicSharedMemorySize, SM_SIZE);

    prologue_kernel<<<1280, 256>>>(x, W, charges, cats, nmask, emb);
    fused_kernel<<<4096, 256, SM_SIZE>>>(bias, edges, out_params, out_radial, out_cd);
}